// round 3
// baseline (speedup 1.0000x reference)
#include <cuda_runtime.h>
#include <math.h>

#define NN 50000
#define EE 800000
#define HH 128
#define FIN 64
#define CC 16
#define LL 3

// ---------------- scratch (static device globals; no allocation) ----------------
__device__ float g_h[NN * HH];          // hidden state  [N,128]
__device__ float g_m[NN * HH];          // messages      [N,128]
__device__ float g_agg[NN * HH];        // aggregated    [N,128]
__device__ float g_r[NN * HH];          // r gate        [N,128]
__device__ float g_z[NN * HH];          // z gate        [N,128]
__device__ float g_Wt[LL * HH * HH];    // per-layer W^T, tf32-rounded: [l][p][k]
__device__ float g_B2[256 * 256];       // fused r/z weights: [col 0..255][k 0..255] tf32
__device__ float g_Bn[2 * HH * HH];     // [0]=w_ih n-rows, [1]=w_hh n-rows, tf32
__device__ float g_b2[256];             // b_ih[j]+b_hh[j] for j<256
__device__ int   g_edge[2 * EE];
__device__ int   g_deg[NN];
__device__ int   g_rowptr[NN + 1];
__device__ int   g_cursor[NN];
__device__ int   g_col[EE];
__device__ int   g_bsum[256];
__device__ int   g_boff[256];
__device__ int   g_is64;

// ---------------- edge dtype probe + normalize ----------------
__global__ void k_detect(const void* ei) {
    if (blockIdx.x == 0 && threadIdx.x == 0) {
        const long long* p64 = (const long long*)ei;
        int ok64 = 1;
        for (int i = 0; i < 64; ++i) {
            long long v = p64[i];
            if (v < 0 || v >= NN) { ok64 = 0; break; }
        }
        g_is64 = ok64;
    }
}

__global__ void k_convert(const void* ei) {
    int e = blockIdx.x * blockDim.x + threadIdx.x;
    if (e < 2 * EE) {
        int v;
        if (g_is64) v = (int)((const long long*)ei)[e];
        else        v = ((const int*)ei)[e];
        g_edge[e] = v;
    }
}

// ---------------- init ----------------
__global__ void k_pad(const float* __restrict__ x) {
    int i = blockIdx.x * blockDim.x + threadIdx.x;
    if (i < NN * HH) {
        int n = i >> 7, k = i & 127;
        g_h[i] = (k < FIN) ? x[n * FIN + k] : 0.f;
    }
}

__device__ __forceinline__ unsigned f2tf(float x) {
    unsigned r;
    asm("cvt.rna.tf32.f32 %0, %1;" : "=r"(r) : "f"(x));
    return r;
}
__device__ __forceinline__ float f2tf_f(float x) {
    return __uint_as_float(f2tf(x));
}

// one prep kernel: Wt, B2, Bn, b2 (all weights tf32-rounded once)
__global__ void k_prep(const float* __restrict__ W,
                       const float* __restrict__ w_ih,
                       const float* __restrict__ w_hh,
                       const float* __restrict__ b_ih,
                       const float* __restrict__ b_hh) {
    int i = blockIdx.x * blockDim.x + threadIdx.x;   // up to 65536
    if (i < 256 * 256) {
        int j = i >> 8, k = i & 255;
        float v = (k < 128) ? w_ih[j * 128 + k] : w_hh[j * 128 + (k - 128)];
        g_B2[i] = f2tf_f(v);
    }
    if (i < LL * HH * HH) {
        int l = i >> 14;
        int k = (i >> 7) & 127;
        int p = i & 127;
        g_Wt[(l << 14) + p * 128 + k] = f2tf_f(W[i]);
    }
    if (i < 2 * HH * HH) {
        int sel = i >> 14, j = (i >> 7) & 127, k = i & 127;
        const float* src = sel ? w_hh : w_ih;
        g_Bn[i] = f2tf_f(src[(256 + j) * 128 + k]);
    }
    if (i < 256) g_b2[i] = b_ih[i] + b_hh[i];
}

// ---------------- CSR build ----------------
__global__ void k_zero_deg() {
    int i = blockIdx.x * blockDim.x + threadIdx.x;
    if (i < NN) g_deg[i] = 0;
}

__global__ void k_hist() {
    int e = blockIdx.x * blockDim.x + threadIdx.x;
    if (e < EE) atomicAdd(&g_deg[g_edge[EE + e]], 1);
}

// 3-phase scan over g_deg -> g_rowptr (exclusive)
__global__ void k_scan1() {
    __shared__ int s[256];
    int t = threadIdx.x;
    int idx = blockIdx.x * 256 + t;
    int v = (idx < NN) ? g_deg[idx] : 0;
    s[t] = v;
    __syncthreads();
#pragma unroll
    for (int off = 1; off < 256; off <<= 1) {
        int add = (t >= off) ? s[t - off] : 0;
        __syncthreads();
        s[t] += add;
        __syncthreads();
    }
    if (idx < NN) g_rowptr[idx] = s[t] - v;     // exclusive within block
    if (t == 255) g_bsum[blockIdx.x] = s[255];
}

__global__ void k_scan2(int nblocks) {
    __shared__ int s[256];
    int t = threadIdx.x;
    int v = (t < nblocks) ? g_bsum[t] : 0;
    s[t] = v;
    __syncthreads();
#pragma unroll
    for (int off = 1; off < 256; off <<= 1) {
        int add = (t >= off) ? s[t - off] : 0;
        __syncthreads();
        s[t] += add;
        __syncthreads();
    }
    if (t < nblocks) g_boff[t] = s[t] - v;      // exclusive block offsets
}

__global__ void k_scan3() {
    int idx = blockIdx.x * 256 + threadIdx.x;
    if (idx < NN) {
        int v = g_rowptr[idx] + g_boff[blockIdx.x];
        g_rowptr[idx] = v;
        g_cursor[idx] = v;
    }
    if (idx == 0) g_rowptr[NN] = EE;
}

__global__ void k_fill() {
    int e = blockIdx.x * blockDim.x + threadIdx.x;
    if (e < EE) {
        int d = g_edge[EE + e];
        int srcn = g_edge[e];
        int pos = atomicAdd(&g_cursor[d], 1);
        g_col[pos] = srcn;
    }
}

// ---------------- aggregation: warp per node, float4 lanes ----------------
__global__ void k_gather() {
    int warp = (blockIdx.x * blockDim.x + threadIdx.x) >> 5;
    int lane = threadIdx.x & 31;
    if (warp >= NN) return;
    int beg = g_rowptr[warp], end = g_rowptr[warp + 1];
    float4 acc = make_float4(0.f, 0.f, 0.f, 0.f);
    int e = beg;
    for (; e + 2 <= end; e += 2) {
        int s0 = g_col[e], s1 = g_col[e + 1];
        float4 v0 = *(const float4*)&g_m[s0 * HH + lane * 4];
        float4 v1 = *(const float4*)&g_m[s1 * HH + lane * 4];
        acc.x += v0.x + v1.x;
        acc.y += v0.y + v1.y;
        acc.z += v0.z + v1.z;
        acc.w += v0.w + v1.w;
    }
    if (e < end) {
        float4 v0 = *(const float4*)&g_m[g_col[e] * HH + lane * 4];
        acc.x += v0.x; acc.y += v0.y; acc.z += v0.z; acc.w += v0.w;
    }
    *(float4*)&g_agg[warp * HH + lane * 4] = acc;
}

// ---------------- tf32 MMA helpers (m16n8k8, block 128x128, BK=32) ----------------
__device__ __forceinline__ void ldA4(float4 rA[4], const float* __restrict__ A,
                                     int row0, int k0, int t) {
#pragma unroll
    for (int q = 0; q < 4; ++q) {
        int idx = q * 256 + t;
        int m = idx >> 3, kq = idx & 7;
        int row = row0 + m;
        rA[q] = (row < NN) ? *(const float4*)&A[row * 128 + k0 + kq * 4]
                           : make_float4(0.f, 0.f, 0.f, 0.f);
    }
}
__device__ __forceinline__ void stA4(unsigned* As, const float4 rA[4], int t) {
#pragma unroll
    for (int q = 0; q < 4; ++q) {
        int idx = q * 256 + t;
        int m = idx >> 3, kq = idx & 7;
        int mf = m >> 4, r16 = m & 15;
        int lb = (r16 & 7) * 4, rh = r16 >> 3;
        int ks = kq >> 1, hi = kq & 1, reg = hi * 2 + rh;
        unsigned* d = &As[(mf * 4 + ks) * 128];
        d[(lb + 0) * 4 + reg] = f2tf(rA[q].x);
        d[(lb + 1) * 4 + reg] = f2tf(rA[q].y);
        d[(lb + 2) * 4 + reg] = f2tf(rA[q].z);
        d[(lb + 3) * 4 + reg] = f2tf(rA[q].w);
    }
}
__device__ __forceinline__ void ldB4(float4 rB[4], const float* __restrict__ B,
                                     int n0, int ldb, int k0, int t) {
#pragma unroll
    for (int q = 0; q < 4; ++q) {
        int idx = q * 256 + t;
        int n = idx >> 3, kq = idx & 7;
        rB[q] = *(const float4*)&B[(n0 + n) * ldb + k0 + kq * 4];
    }
}
__device__ __forceinline__ void stB4(unsigned* Bs, const float4 rB[4], int t) {
#pragma unroll
    for (int q = 0; q < 4; ++q) {
        int idx = q * 256 + t;
        int n = idx >> 3, kq = idx & 7;
        int nf = n >> 3, nl = n & 7;
        int ks = kq >> 1, hi = kq & 1;
        unsigned* d = &Bs[(nf * 4 + ks) * 64];
        d[(nl * 4 + 0) * 2 + hi] = __float_as_uint(rB[q].x);
        d[(nl * 4 + 1) * 2 + hi] = __float_as_uint(rB[q].y);
        d[(nl * 4 + 2) * 2 + hi] = __float_as_uint(rB[q].z);
        d[(nl * 4 + 3) * 2 + hi] = __float_as_uint(rB[q].w);
    }
}
__device__ __forceinline__ void mma16(const unsigned* As, const unsigned* Bs,
                                      float c[4][4][4], int wm, int wn, int lane) {
#pragma unroll
    for (int ks = 0; ks < 4; ++ks) {
        uint4 a[4];
        uint2 b[4];
#pragma unroll
        for (int i = 0; i < 4; ++i)
            a[i] = *(const uint4*)&As[((wm * 4 + i) * 4 + ks) * 128 + lane * 4];
#pragma unroll
        for (int j = 0; j < 4; ++j)
            b[j] = *(const uint2*)&Bs[((wn * 4 + j) * 4 + ks) * 64 + lane * 2];
#pragma unroll
        for (int i = 0; i < 4; ++i)
#pragma unroll
            for (int j = 0; j < 4; ++j)
                asm volatile(
                    "mma.sync.aligned.m16n8k8.row.col.f32.tf32.tf32.f32 "
                    "{%0,%1,%2,%3}, {%4,%5,%6,%7}, {%8,%9}, {%0,%1,%2,%3};"
                    : "+f"(c[i][j][0]), "+f"(c[i][j][1]),
                      "+f"(c[i][j][2]), "+f"(c[i][j][3])
                    : "r"(a[i].x), "r"(a[i].y), "r"(a[i].z), "r"(a[i].w),
                      "r"(b[j].x), "r"(b[j].y));
    }
}

// ---------------- m = h @ W_l  (prefetch double-buffered) ----------------
__global__ __launch_bounds__(256) void k_mma_m(const float* __restrict__ B) {
    __shared__ unsigned As[4096], Bs[4096];
    int t = threadIdx.x, lane = t & 31, w = t >> 5, wm = w >> 2, wn = w & 3;
    int row0 = blockIdx.x * 128;
    float c[4][4][4];
#pragma unroll
    for (int i = 0; i < 4; ++i)
#pragma unroll
        for (int j = 0; j < 4; ++j)
#pragma unroll
            for (int r = 0; r < 4; ++r) c[i][j][r] = 0.f;

    float4 rA[4], rB[4];
    ldA4(rA, g_h, row0, 0, t);
    ldB4(rB, B, 0, 128, 0, t);
    stA4(As, rA, t);
    stB4(Bs, rB, t);
    __syncthreads();
#pragma unroll
    for (int cc = 0; cc < 4; ++cc) {
        if (cc < 3) {
            ldA4(rA, g_h, row0, (cc + 1) * 32, t);
            ldB4(rB, B, 0, 128, (cc + 1) * 32, t);
        }
        mma16(As, Bs, c, wm, wn, lane);
        __syncthreads();
        if (cc < 3) {
            stA4(As, rA, t);
            stB4(Bs, rB, t);
            __syncthreads();
        }
    }
#pragma unroll
    for (int i = 0; i < 4; ++i)
#pragma unroll
        for (int j = 0; j < 4; ++j) {
            int r = row0 + wm * 64 + i * 16 + (lane >> 2);
            int gc = wn * 32 + j * 8 + (lane & 3) * 2;
            if (r < NN)
                *(float2*)&g_m[r * 128 + gc] = make_float2(c[i][j][0], c[i][j][1]);
            if (r + 8 < NN)
                *(float2*)&g_m[(r + 8) * 128 + gc] = make_float2(c[i][j][2], c[i][j][3]);
        }
}

// ---------------- r,z gates: fused K=256 GEMM over [agg|h] ----------------
__global__ __launch_bounds__(256) void k_rz() {
    __shared__ unsigned As[4096], Bs[4096];
    int t = threadIdx.x, lane = t & 31, w = t >> 5, wm = w >> 2, wn = w & 3;
    int row0 = blockIdx.x * 128;
    int n0 = blockIdx.y * 128;
    float c[4][4][4];
#pragma unroll
    for (int i = 0; i < 4; ++i)
#pragma unroll
        for (int j = 0; j < 4; ++j)
#pragma unroll
            for (int r = 0; r < 4; ++r) c[i][j][r] = 0.f;

    float4 rA[4], rB[4];
    ldA4(rA, g_agg, row0, 0, t);
    ldB4(rB, g_B2, n0, 256, 0, t);
    stA4(As, rA, t);
    stB4(Bs, rB, t);
    __syncthreads();
#pragma unroll
    for (int cc = 0; cc < 8; ++cc) {
        if (cc < 7) {
            int c1 = cc + 1;
            const float* srcA = (c1 < 4) ? g_agg : g_h;
            ldA4(rA, srcA, row0, (c1 & 3) * 32, t);
            ldB4(rB, g_B2, n0, 256, c1 * 32, t);
        }
        mma16(As, Bs, c, wm, wn, lane);
        __syncthreads();
        if (cc < 7) {
            stA4(As, rA, t);
            stB4(Bs, rB, t);
            __syncthreads();
        }
    }
    float* out = (n0 == 0) ? g_r : g_z;
#pragma unroll
    for (int i = 0; i < 4; ++i)
#pragma unroll
        for (int j = 0; j < 4; ++j) {
            int r = row0 + wm * 64 + i * 16 + (lane >> 2);
            int lc = wn * 32 + j * 8 + (lane & 3) * 2;   // local col 0..127
            float b0 = g_b2[n0 + lc], b1 = g_b2[n0 + lc + 1];
            if (r < NN) {
                float v0 = 1.f / (1.f + expf(-(c[i][j][0] + b0)));
                float v1 = 1.f / (1.f + expf(-(c[i][j][1] + b1)));
                *(float2*)&out[r * 128 + lc] = make_float2(v0, v1);
            }
            if (r + 8 < NN) {
                float v0 = 1.f / (1.f + expf(-(c[i][j][2] + b0)));
                float v1 = 1.f / (1.f + expf(-(c[i][j][3] + b1)));
                *(float2*)&out[(r + 8) * 128 + lc] = make_float2(v0, v1);
            }
        }
}

// ---------------- n gate + GRU update: dual GEMM, writes h in place ----------------
__global__ __launch_bounds__(256) void k_n(const float* __restrict__ b_ih,
                                           const float* __restrict__ b_hh) {
    __shared__ unsigned As[4096], Bs[4096];
    int t = threadIdx.x, lane = t & 31, w = t >> 5, wm = w >> 2, wn = w & 3;
    int row0 = blockIdx.x * 128;
    float ci[4][4][4], ch[4][4][4];
#pragma unroll
    for (int i = 0; i < 4; ++i)
#pragma unroll
        for (int j = 0; j < 4; ++j)
#pragma unroll
            for (int r = 0; r < 4; ++r) { ci[i][j][r] = 0.f; ch[i][j][r] = 0.f; }

    float4 rA[4], rB[4];
#pragma unroll
    for (int cc = 0; cc < 4; ++cc) {
        int k0 = cc * 32;
        // in_ = agg @ Wn_i^T
        ldA4(rA, g_agg, row0, k0, t);
        ldB4(rB, g_Bn, 0, 128, k0, t);
        stA4(As, rA, t);
        stB4(Bs, rB, t);
        __syncthreads();
        mma16(As, Bs, ci, wm, wn, lane);
        __syncthreads();
        // hn = h @ Wn_h^T
        ldA4(rA, g_h, row0, k0, t);
        ldB4(rB, g_Bn + 16384, 0, 128, k0, t);
        stA4(As, rA, t);
        stB4(Bs, rB, t);
        __syncthreads();
        mma16(As, Bs, ch, wm, wn, lane);
        __syncthreads();
    }
    // GRU epilogue: h' = (1-z)*tanh(in_+ r*hn) + z*h
#pragma unroll
    for (int i = 0; i < 4; ++i)
#pragma unroll
        for (int j = 0; j < 4; ++j) {
            int r0 = row0 + wm * 64 + i * 16 + (lane >> 2);
            int lc = wn * 32 + j * 8 + (lane & 3) * 2;
            float bi0 = b_ih[256 + lc], bi1 = b_ih[256 + lc + 1];
            float bh0 = b_hh[256 + lc], bh1 = b_hh[256 + lc + 1];
#pragma unroll
            for (int half = 0; half < 2; ++half) {
                int row = r0 + half * 8;
                if (row < NN) {
                    float2 rr = *(const float2*)&g_r[row * 128 + lc];
                    float2 zz = *(const float2*)&g_z[row * 128 + lc];
                    float2 ho = *(const float2*)&g_h[row * 128 + lc];
                    float in0 = ci[i][j][half * 2 + 0] + bi0;
                    float in1 = ci[i][j][half * 2 + 1] + bi1;
                    float hn0 = ch[i][j][half * 2 + 0] + bh0;
                    float hn1 = ch[i][j][half * 2 + 1] + bh1;
                    float n0v = tanhf(in0 + rr.x * hn0);
                    float n1v = tanhf(in1 + rr.y * hn1);
                    float2 o = make_float2((1.f - zz.x) * n0v + zz.x * ho.x,
                                           (1.f - zz.y) * n1v + zz.y * ho.y);
                    *(float2*)&g_h[row * 128 + lc] = o;
                }
            }
        }
}

// ---------------- classifier + log_softmax ----------------
__global__ void k_cls(const float* __restrict__ lw, const float* __restrict__ lb,
                      float* __restrict__ out) {
    int gt = blockIdx.x * blockDim.x + threadIdx.x;
    int row = gt >> 5;
    int lane = gt & 31;
    if (row >= NN) return;
    const float* hrow = g_h + row * 128;
    float acc[CC];
#pragma unroll
    for (int c = 0; c < CC; ++c) acc[c] = 0.f;
#pragma unroll
    for (int kq = 0; kq < 4; ++kq) {
        int k = lane + kq * 32;
        float hv = hrow[k];
#pragma unroll
        for (int c = 0; c < CC; ++c) acc[c] += hv * lw[c * 128 + k];
    }
#pragma unroll
    for (int c = 0; c < CC; ++c) {
#pragma unroll
        for (int off = 16; off; off >>= 1)
            acc[c] += __shfl_xor_sync(0xffffffffu, acc[c], off);
        acc[c] += lb[c];
    }
    float mx = acc[0];
#pragma unroll
    for (int c = 1; c < CC; ++c) mx = fmaxf(mx, acc[c]);
    float se = 0.f;
#pragma unroll
    for (int c = 0; c < CC; ++c) se += expf(acc[c] - mx);
    float lse = mx + logf(se);
    if (lane < CC) out[row * CC + lane] = acc[lane] - lse;
}

// ---------------- launch ----------------
extern "C" void kernel_launch(void* const* d_in, const int* in_sizes, int n_in,
                              void* d_out, int out_size) {
    const float* x     = (const float*)d_in[0];
    const void*  ei    = d_in[1];
    const float* W     = (const float*)d_in[2];
    const float* w_ih  = (const float*)d_in[3];
    const float* w_hh  = (const float*)d_in[4];
    const float* b_ih  = (const float*)d_in[5];
    const float* b_hh  = (const float*)d_in[6];
    const float* lw    = (const float*)d_in[7];
    const float* lb    = (const float*)d_in[8];
    float* out = (float*)d_out;

    float* p_Wt;
    cudaGetSymbolAddress((void**)&p_Wt, g_Wt);

    const int NSCAN = (NN + 255) / 256;   // 196

    k_detect<<<1, 32>>>(ei);
    k_convert<<<(2 * EE + 255) / 256, 256>>>(ei);
    k_pad<<<(NN * HH + 255) / 256, 256>>>(x);
    k_prep<<<256, 256>>>(W, w_ih, w_hh, b_ih, b_hh);
    k_zero_deg<<<NSCAN, 256>>>();
    k_hist<<<(EE + 255) / 256, 256>>>();
    k_scan1<<<NSCAN, 256>>>();
    k_scan2<<<1, 256>>>(NSCAN);
    k_scan3<<<NSCAN, 256>>>();
    k_fill<<<(EE + 255) / 256, 256>>>();

    const int GB = (NN + 127) / 128;      // 391
    dim3 grz(GB, 2);
    for (int l = 0; l < LL; ++l) {
        k_mma_m<<<GB, 256>>>(p_Wt + l * HH * HH);
        k_gather<<<(NN * 32 + 255) / 256, 256>>>();
        k_rz<<<grz, 256>>>();
        k_n<<<GB, 256>>>(b_ih, b_hh);
    }
    k_cls<<<(NN * 32 + 255) / 256, 256>>>(lw, lb, out);
}

// round 5
// speedup vs baseline: 1.4530x; 1.4530x over previous
#include <cuda_runtime.h>
#include <math.h>

#define NN 50000
#define EE 800000
#define HH 128
#define FIN 64
#define CC 16
#define LL 3

// ---------------- scratch (static device globals; no allocation) ----------------
__device__ float g_h[NN * HH];          // hidden state  [N,128]
__device__ float g_m[NN * HH];          // messages      [N,128]
__device__ float g_agg[NN * HH];        // aggregated    [N,128]
__device__ float g_gi[NN * 3 * HH];     // input gates   [N,384]
__device__ float g_gh[NN * 3 * HH];     // hidden gates  [N,384]
__device__ float g_Wt[LL * HH * HH];    // per-layer W^T, tf32-rounded: [l][p][k]
__device__ float g_Wih[3 * HH * HH];    // w_ih tf32-rounded [384][128]
__device__ float g_Whh[3 * HH * HH];    // w_hh tf32-rounded [384][128]
__device__ int   g_edge[2 * EE];
__device__ int   g_deg[NN];
__device__ int   g_rowptr[NN + 1];
__device__ int   g_cursor[NN];
__device__ int   g_col[EE];
__device__ int   g_bsum[256];
__device__ int   g_boff[256];
__device__ int   g_is64;

// ---------------- edge dtype probe + normalize ----------------
__global__ void k_detect(const void* ei) {
    if (blockIdx.x == 0 && threadIdx.x == 0) {
        const long long* p64 = (const long long*)ei;
        int ok64 = 1;
        for (int i = 0; i < 64; ++i) {
            long long v = p64[i];
            if (v < 0 || v >= NN) { ok64 = 0; break; }
        }
        g_is64 = ok64;
    }
}

__global__ void k_convert(const void* ei) {
    int e = blockIdx.x * blockDim.x + threadIdx.x;
    if (e < 2 * EE) {
        int v;
        if (g_is64) v = (int)((const long long*)ei)[e];
        else        v = ((const int*)ei)[e];
        g_edge[e] = v;
    }
}

// ---------------- init ----------------
__global__ void k_pad(const float* __restrict__ x) {
    int i = blockIdx.x * blockDim.x + threadIdx.x;
    if (i < NN * HH) {
        int n = i >> 7, k = i & 127;
        g_h[i] = (k < FIN) ? x[n * FIN + k] : 0.f;
    }
}

__device__ __forceinline__ unsigned f2tf(float x) {
    unsigned r;
    asm("cvt.rna.tf32.f32 %0, %1;" : "=r"(r) : "f"(x));
    return r;
}
__device__ __forceinline__ float f2tf_f(float x) {
    return __uint_as_float(f2tf(x));
}

// pre-round all GEMM B operands to tf32 once
__global__ void k_prep(const float* __restrict__ W,
                       const float* __restrict__ w_ih,
                       const float* __restrict__ w_hh) {
    int i = blockIdx.x * blockDim.x + threadIdx.x;   // 65536 threads
    if (i < LL * HH * HH) {
        int l = i >> 14;
        int k = (i >> 7) & 127;
        int p = i & 127;
        g_Wt[(l << 14) + p * 128 + k] = f2tf_f(W[i]);   // Wt[l][p][k] = W[l][k][p]
    }
    if (i < 3 * HH * HH) {
        g_Wih[i] = f2tf_f(w_ih[i]);
        g_Whh[i] = f2tf_f(w_hh[i]);
    }
}

// ---------------- CSR build ----------------
__global__ void k_zero_deg() {
    int i = blockIdx.x * blockDim.x + threadIdx.x;
    if (i < NN) g_deg[i] = 0;
}

__global__ void k_hist() {
    int e = blockIdx.x * blockDim.x + threadIdx.x;
    if (e < EE) atomicAdd(&g_deg[g_edge[EE + e]], 1);
}

// 3-phase multi-block exclusive scan: g_deg -> g_rowptr (+cursor init)
__global__ void k_scan1() {
    __shared__ int s[256];
    int t = threadIdx.x;
    int idx = blockIdx.x * 256 + t;
    int v = (idx < NN) ? g_deg[idx] : 0;
    s[t] = v;
    __syncthreads();
#pragma unroll
    for (int off = 1; off < 256; off <<= 1) {
        int add = (t >= off) ? s[t - off] : 0;
        __syncthreads();
        s[t] += add;
        __syncthreads();
    }
    if (idx < NN) g_rowptr[idx] = s[t] - v;
    if (t == 255) g_bsum[blockIdx.x] = s[255];
}

__global__ void k_scan2(int nblocks) {
    __shared__ int s[256];
    int t = threadIdx.x;
    int v = (t < nblocks) ? g_bsum[t] : 0;
    s[t] = v;
    __syncthreads();
#pragma unroll
    for (int off = 1; off < 256; off <<= 1) {
        int add = (t >= off) ? s[t - off] : 0;
        __syncthreads();
        s[t] += add;
        __syncthreads();
    }
    if (t < nblocks) g_boff[t] = s[t] - v;
}

__global__ void k_scan3() {
    int idx = blockIdx.x * 256 + threadIdx.x;
    if (idx < NN) {
        int v = g_rowptr[idx] + g_boff[blockIdx.x];
        g_rowptr[idx] = v;
        g_cursor[idx] = v;
    }
    if (idx == 0) g_rowptr[NN] = EE;
}

__global__ void k_fill() {
    int e = blockIdx.x * blockDim.x + threadIdx.x;
    if (e < EE) {
        int d = g_edge[EE + e];
        int srcn = g_edge[e];
        int pos = atomicAdd(&g_cursor[d], 1);
        g_col[pos] = srcn;
    }
}

// ---------------- aggregation (round-2 proven: block of 128 per node) ----------------
__global__ void k_gather() {
    int n = blockIdx.x;
    int t = threadIdx.x;
    int beg = g_rowptr[n], end = g_rowptr[n + 1];
    float acc = 0.f;
    int e = beg;
    for (; e + 4 <= end; e += 4) {
        int s0 = g_col[e], s1 = g_col[e + 1], s2 = g_col[e + 2], s3 = g_col[e + 3];
        acc += g_m[s0 * HH + t];
        acc += g_m[s1 * HH + t];
        acc += g_m[s2 * HH + t];
        acc += g_m[s3 * HH + t];
    }
    for (; e < end; ++e) acc += g_m[g_col[e] * HH + t];
    g_agg[n * HH + t] = acc;
}

// ---------------- tf32 tensor-core GEMM (round-2 structure, occupancy pinned) ----------------
// C[r, n0+col] = sum_k A[r][k] * Bt[n0+col][k] (+ bias), K = 128, Bt pre-tf32.
__global__ __launch_bounds__(256, 2) void k_mma(const float* __restrict__ A,
                                                const float* __restrict__ Bt,
                                                const float* __restrict__ bias,
                                                float* __restrict__ C, int ldc) {
    __shared__ unsigned As[4096];   // [mf(8)][ks(4)][lane(32)][reg(4)]
    __shared__ unsigned Bs[4096];   // [nf(16)][ks(4)][lane(32)][reg(2)]
    int t = threadIdx.x;
    int lane = t & 31, w = t >> 5;
    int wm = w >> 2, wn = w & 3;
    int row0 = blockIdx.x * 128;
    int n0 = blockIdx.y * 128;

    float c[4][4][4];
#pragma unroll
    for (int i = 0; i < 4; ++i)
#pragma unroll
        for (int j = 0; j < 4; ++j)
#pragma unroll
            for (int r = 0; r < 4; ++r) c[i][j][r] = 0.f;

    for (int cc = 0; cc < 4; ++cc) {
        int k0 = cc * 32;
        // ---- stage A chunk (convert to tf32 here) ----
#pragma unroll
        for (int q = 0; q < 4; ++q) {
            int idx = q * 256 + t;
            int m = idx >> 3, kq = idx & 7;
            int row = row0 + m;
            float4 v = make_float4(0.f, 0.f, 0.f, 0.f);
            if (row < NN) v = *(const float4*)&A[row * 128 + k0 + kq * 4];
            int mf = m >> 4, r16 = m & 15;
            int lanebase = (r16 & 7) * 4;
            int reghalf = r16 >> 3;
            int ks = kq >> 1, hi = kq & 1;
            int reg = hi * 2 + reghalf;
            unsigned* dst = &As[(mf * 4 + ks) * 128];
            dst[(lanebase + 0) * 4 + reg] = f2tf(v.x);
            dst[(lanebase + 1) * 4 + reg] = f2tf(v.y);
            dst[(lanebase + 2) * 4 + reg] = f2tf(v.z);
            dst[(lanebase + 3) * 4 + reg] = f2tf(v.w);
        }
        // ---- stage B chunk (already tf32; raw bit move) ----
#pragma unroll
        for (int q = 0; q < 4; ++q) {
            int idx = q * 256 + t;
            int n = idx >> 3, kq = idx & 7;
            float4 v = *(const float4*)&Bt[(n0 + n) * 128 + k0 + kq * 4];
            int nf = n >> 3, nl = n & 7;
            int ks = kq >> 1, hi = kq & 1;
            unsigned* dst = &Bs[(nf * 4 + ks) * 64];
            dst[(nl * 4 + 0) * 2 + hi] = __float_as_uint(v.x);
            dst[(nl * 4 + 1) * 2 + hi] = __float_as_uint(v.y);
            dst[(nl * 4 + 2) * 2 + hi] = __float_as_uint(v.z);
            dst[(nl * 4 + 3) * 2 + hi] = __float_as_uint(v.w);
        }
        __syncthreads();
        // ---- compute ----
#pragma unroll
        for (int ks = 0; ks < 4; ++ks) {
            uint4 a[4];
            uint2 b[4];
#pragma unroll
            for (int i = 0; i < 4; ++i)
                a[i] = *(const uint4*)&As[((wm * 4 + i) * 4 + ks) * 128 + lane * 4];
#pragma unroll
            for (int j = 0; j < 4; ++j)
                b[j] = *(const uint2*)&Bs[((wn * 4 + j) * 4 + ks) * 64 + lane * 2];
#pragma unroll
            for (int i = 0; i < 4; ++i)
#pragma unroll
                for (int j = 0; j < 4; ++j) {
                    asm volatile(
                        "mma.sync.aligned.m16n8k8.row.col.f32.tf32.tf32.f32 "
                        "{%0,%1,%2,%3}, {%4,%5,%6,%7}, {%8,%9}, {%0,%1,%2,%3};"
                        : "+f"(c[i][j][0]), "+f"(c[i][j][1]),
                          "+f"(c[i][j][2]), "+f"(c[i][j][3])
                        : "r"(a[i].x), "r"(a[i].y), "r"(a[i].z), "r"(a[i].w),
                          "r"(b[j].x), "r"(b[j].y));
                }
        }
        __syncthreads();
    }
    // ---- epilogue ----
#pragma unroll
    for (int i = 0; i < 4; ++i) {
#pragma unroll
        for (int j = 0; j < 4; ++j) {
            int r = row0 + wm * 64 + i * 16 + (lane >> 2);
            int gcol = n0 + wn * 32 + j * 8 + (lane & 3) * 2;
            float b0 = 0.f, b1 = 0.f;
            if (bias) { b0 = bias[gcol]; b1 = bias[gcol + 1]; }
            if (r < NN) {
                float2 o = make_float2(c[i][j][0] + b0, c[i][j][1] + b1);
                *(float2*)&C[r * ldc + gcol] = o;
            }
            if (r + 8 < NN) {
                float2 o = make_float2(c[i][j][2] + b0, c[i][j][3] + b1);
                *(float2*)&C[(r + 8) * ldc + gcol] = o;
            }
        }
    }
}

// ---------------- GRU gates (torch order r, z, n) ----------------
__global__ void k_gru() {
    int i = blockIdx.x * blockDim.x + threadIdx.x;
    if (i >= NN * HH) return;
    int n = i >> 7, j = i & 127;
    const float* gi = g_gi + n * 384;
    const float* gh = g_gh + n * 384;
    float r = 1.f / (1.f + expf(-(gi[j] + gh[j])));
    float z = 1.f / (1.f + expf(-(gi[128 + j] + gh[128 + j])));
    float nn = tanhf(gi[256 + j] + r * gh[256 + j]);
    float h = g_h[i];
    g_h[i] = (1.f - z) * nn + z * h;
}

// ---------------- classifier + log_softmax ----------------
__global__ void k_cls(const float* __restrict__ lw, const float* __restrict__ lb,
                      float* __restrict__ out) {
    int gt = blockIdx.x * blockDim.x + threadIdx.x;
    int row = gt >> 5;
    int lane = gt & 31;
    if (row >= NN) return;
    const float* hrow = g_h + row * 128;
    float acc[CC];
#pragma unroll
    for (int c = 0; c < CC; ++c) acc[c] = 0.f;
#pragma unroll
    for (int kq = 0; kq < 4; ++kq) {
        int k = lane + kq * 32;
        float hv = hrow[k];
#pragma unroll
        for (int c = 0; c < CC; ++c) acc[c] += hv * lw[c * 128 + k];
    }
#pragma unroll
    for (int c = 0; c < CC; ++c) {
#pragma unroll
        for (int off = 16; off; off >>= 1)
            acc[c] += __shfl_xor_sync(0xffffffffu, acc[c], off);
        acc[c] += lb[c];
    }
    float mx = acc[0];
#pragma unroll
    for (int c = 1; c < CC; ++c) mx = fmaxf(mx, acc[c]);
    float se = 0.f;
#pragma unroll
    for (int c = 0; c < CC; ++c) se += expf(acc[c] - mx);
    float lse = mx + logf(se);
    if (lane < CC) out[row * CC + lane] = acc[lane] - lse;
}

// ---------------- launch ----------------
extern "C" void kernel_launch(void* const* d_in, const int* in_sizes, int n_in,
                              void* d_out, int out_size) {
    const float* x     = (const float*)d_in[0];
    const void*  ei    = d_in[1];
    const float* W     = (const float*)d_in[2];
    const float* w_ih  = (const float*)d_in[3];
    const float* w_hh  = (const float*)d_in[4];
    const float* b_ih  = (const float*)d_in[5];
    const float* b_hh  = (const float*)d_in[6];
    const float* lw    = (const float*)d_in[7];
    const float* lb    = (const float*)d_in[8];
    float* out = (float*)d_out;

    float *p_h, *p_m, *p_agg, *p_gi, *p_gh, *p_Wt, *p_Wih, *p_Whh;
    cudaGetSymbolAddress((void**)&p_h,   g_h);
    cudaGetSymbolAddress((void**)&p_m,   g_m);
    cudaGetSymbolAddress((void**)&p_agg, g_agg);
    cudaGetSymbolAddress((void**)&p_gi,  g_gi);
    cudaGetSymbolAddress((void**)&p_gh,  g_gh);
    cudaGetSymbolAddress((void**)&p_Wt,  g_Wt);
    cudaGetSymbolAddress((void**)&p_Wih, g_Wih);
    cudaGetSymbolAddress((void**)&p_Whh, g_Whh);

    const int NSCAN = (NN + 255) / 256;   // 196

    k_detect<<<1, 32>>>(ei);
    k_convert<<<(2 * EE + 255) / 256, 256>>>(ei);
    k_pad<<<(NN * HH + 255) / 256, 256>>>(x);
    k_prep<<<256, 256>>>(W, w_ih, w_hh);
    k_zero_deg<<<NSCAN, 256>>>();
    k_hist<<<(EE + 255) / 256, 256>>>();
    k_scan1<<<NSCAN, 256>>>();
    k_scan2<<<1, 256>>>(NSCAN);
    k_scan3<<<NSCAN, 256>>>();
    k_fill<<<(EE + 255) / 256, 256>>>();

    dim3 gm((NN + 127) / 128, 1);
    dim3 gg((NN + 127) / 128, 3);
    for (int l = 0; l < LL; ++l) {
        k_mma<<<gm, 256>>>(p_h, p_Wt + l * HH * HH, nullptr, p_m, 128);
        k_gather<<<NN, 128>>>();
        k_mma<<<gg, 256>>>(p_agg, p_Wih, b_ih, p_gi, 384);
        k_mma<<<gg, 256>>>(p_h, p_Whh, b_hh, p_gh, 384);
        k_gru<<<(NN * HH + 255) / 256, 256>>>();
    }
    k_cls<<<(NN * 32 + 255) / 256, 256>>>(lw, lb, out);
}

// round 6
// speedup vs baseline: 1.5500x; 1.0668x over previous
#include <cuda_runtime.h>
#include <math.h>

#define NN 50000
#define EE 800000
#define HH 128
#define FIN 64
#define CC 16
#define LL 3

// ---------------- scratch (static device globals; no allocation) ----------------
__device__ float g_h[NN * HH];          // hidden state  [N,128]
__device__ float g_m[NN * HH];          // messages      [N,128]
__device__ float g_agg[NN * HH];        // aggregated    [N,128]
__device__ float g_gi[NN * 3 * HH];     // input gates   [N,384]
__device__ float g_gh[NN * 3 * HH];     // hidden gates  [N,384]
__device__ unsigned g_Wtp[LL * HH * HH];   // W^T per layer, tf32 FRAGMENT-PERMUTED
__device__ unsigned g_Wihp[3 * HH * HH];   // w_ih tf32 fragment-permuted
__device__ unsigned g_Whhp[3 * HH * HH];   // w_hh tf32 fragment-permuted
__device__ int   g_edge[2 * EE];
__device__ int   g_deg[NN];
__device__ int   g_rowptr[NN + 1];
__device__ int   g_cursor[NN];
__device__ int   g_col[EE];
__device__ int   g_bsum[256];
__device__ int   g_boff[256];
__device__ int   g_is64;

// ---------------- edge dtype probe + normalize ----------------
__global__ void k_detect(const void* ei) {
    if (blockIdx.x == 0 && threadIdx.x == 0) {
        const long long* p64 = (const long long*)ei;
        int ok64 = 1;
        for (int i = 0; i < 64; ++i) {
            long long v = p64[i];
            if (v < 0 || v >= NN) { ok64 = 0; break; }
        }
        g_is64 = ok64;
    }
}

__global__ void k_convert(const void* ei) {
    int e = blockIdx.x * blockDim.x + threadIdx.x;
    if (e < 2 * EE) {
        int v;
        if (g_is64) v = (int)((const long long*)ei)[e];
        else        v = ((const int*)ei)[e];
        g_edge[e] = v;
    }
}

// ---------------- init ----------------
__global__ void k_pad(const float* __restrict__ x) {
    int i = blockIdx.x * blockDim.x + threadIdx.x;
    if (i < NN * HH) {
        int n = i >> 7, k = i & 127;
        g_h[i] = (k < FIN) ? x[n * FIN + k] : 0.f;
    }
}

__device__ __forceinline__ unsigned f2tf(float x) {
    unsigned r;
    asm("cvt.rna.tf32.f32 %0, %1;" : "=r"(r) : "f"(x));
    return r;
}

// Fragment-permuted B layout for mma.m16n8k8 tf32 B operand.
// For a B matrix addressed as value(n, k) with n in [0,Ntot), k in [0,128):
//   g  = n >> 7 (128-col group), nf = (n>>3)&15, nl = n&7
//   ks = k >> 3, hi = (k&7)>>2, c = k&3, lane = nl*4 + c
//   offset = ((g*16 + nf)*16 + ks)*64 + lane*2 + hi
__device__ __forceinline__ int bperm_off(int n, int k) {
    int g = n >> 7, nf = (n >> 3) & 15, nl = n & 7;
    int ks = k >> 3, hi = (k & 7) >> 2, c = k & 3;
    int lane = nl * 4 + c;
    return ((g * 16 + nf) * 16 + ks) * 64 + lane * 2 + hi;
}

// pre-round + pre-permute all GEMM B operands once
__global__ void k_prep(const float* __restrict__ W,
                       const float* __restrict__ w_ih,
                       const float* __restrict__ w_hh) {
    int i = blockIdx.x * blockDim.x + threadIdx.x;   // 65536 threads
    if (i < LL * HH * HH) {
        int l = i >> 14;
        int rem = i & 16383;
        int n = rem >> 7, k = rem & 127;             // Bt[n][k] = W[l][k][n]
        g_Wtp[(l << 14) + bperm_off(n, k)] = f2tf(W[(l << 14) + k * 128 + n]);
    }
    if (i < 3 * HH * HH) {
        int n = i >> 7, k = i & 127;
        int off = bperm_off(n, k);
        g_Wihp[off] = f2tf(w_ih[i]);
        g_Whhp[off] = f2tf(w_hh[i]);
    }
}

// ---------------- CSR build ----------------
__global__ void k_zero_deg() {
    int i = blockIdx.x * blockDim.x + threadIdx.x;
    if (i < NN) g_deg[i] = 0;
}

__global__ void k_hist() {
    int e = blockIdx.x * blockDim.x + threadIdx.x;
    if (e < EE) atomicAdd(&g_deg[g_edge[EE + e]], 1);
}

// 3-phase multi-block exclusive scan: g_deg -> g_rowptr (+cursor init)
__global__ void k_scan1() {
    __shared__ int s[256];
    int t = threadIdx.x;
    int idx = blockIdx.x * 256 + t;
    int v = (idx < NN) ? g_deg[idx] : 0;
    s[t] = v;
    __syncthreads();
#pragma unroll
    for (int off = 1; off < 256; off <<= 1) {
        int add = (t >= off) ? s[t - off] : 0;
        __syncthreads();
        s[t] += add;
        __syncthreads();
    }
    if (idx < NN) g_rowptr[idx] = s[t] - v;
    if (t == 255) g_bsum[blockIdx.x] = s[255];
}

__global__ void k_scan2(int nblocks) {
    __shared__ int s[256];
    int t = threadIdx.x;
    int v = (t < nblocks) ? g_bsum[t] : 0;
    s[t] = v;
    __syncthreads();
#pragma unroll
    for (int off = 1; off < 256; off <<= 1) {
        int add = (t >= off) ? s[t - off] : 0;
        __syncthreads();
        s[t] += add;
        __syncthreads();
    }
    if (t < nblocks) g_boff[t] = s[t] - v;
}

__global__ void k_scan3() {
    int idx = blockIdx.x * 256 + threadIdx.x;
    if (idx < NN) {
        int v = g_rowptr[idx] + g_boff[blockIdx.x];
        g_rowptr[idx] = v;
        g_cursor[idx] = v;
    }
    if (idx == 0) g_rowptr[NN] = EE;
}

__global__ void k_fill() {
    int e = blockIdx.x * blockDim.x + threadIdx.x;
    if (e < EE) {
        int d = g_edge[EE + e];
        int srcn = g_edge[e];
        int pos = atomicAdd(&g_cursor[d], 1);
        g_col[pos] = srcn;
    }
}

// ---------------- aggregation (proven: block of 128 per node) ----------------
__global__ void k_gather() {
    int n = blockIdx.x;
    int t = threadIdx.x;
    int beg = g_rowptr[n], end = g_rowptr[n + 1];
    float acc = 0.f;
    int e = beg;
    for (; e + 4 <= end; e += 4) {
        int s0 = g_col[e], s1 = g_col[e + 1], s2 = g_col[e + 2], s3 = g_col[e + 3];
        acc += g_m[s0 * HH + t];
        acc += g_m[s1 * HH + t];
        acc += g_m[s2 * HH + t];
        acc += g_m[s3 * HH + t];
    }
    for (; e < end; ++e) acc += g_m[g_col[e] * HH + t];
    g_agg[n * HH + t] = acc;
}

// ---------------- tf32 tensor-core GEMM ----------------
// C[r, n0+col] = sum_k A[r][k] * B(n0+col, k) (+ bias), K=128.
// BK=64 (2 chunks), A in smem (fragment-permuted), B fragments loaded
// per-lane DIRECTLY from pre-permuted global (L1/L2-hot across all blocks).
__global__ __launch_bounds__(256, 2) void k_mma(const float* __restrict__ A,
                                                const unsigned* __restrict__ Bp,
                                                const float* __restrict__ bias,
                                                float* __restrict__ C, int ldc) {
    __shared__ unsigned As[8192];   // [mf(8)][ks(8)][lane(32)][reg(4)] = 32KB
    int t = threadIdx.x;
    int lane = t & 31, w = t >> 5;
    int wm = w >> 2, wn = w & 3;
    int row0 = blockIdx.x * 128;
    int g = blockIdx.y;             // 128-col group
    const unsigned* Bg = Bp + g * 16384;

    float c[4][4][4];
#pragma unroll
    for (int i = 0; i < 4; ++i)
#pragma unroll
        for (int j = 0; j < 4; ++j)
#pragma unroll
            for (int r = 0; r < 4; ++r) c[i][j][r] = 0.f;

#pragma unroll
    for (int cc = 0; cc < 2; ++cc) {
        int k0 = cc * 64;
        // ---- stage A chunk (128 rows x 64 k), cvt to tf32, fragment layout ----
#pragma unroll
        for (int q = 0; q < 8; ++q) {
            int idx = q * 256 + t;
            int m = idx >> 4, kq = idx & 15;       // kq: quad of 4 within 64-k
            int row = row0 + m;
            float4 v = make_float4(0.f, 0.f, 0.f, 0.f);
            if (row < NN) v = *(const float4*)&A[row * 128 + k0 + kq * 4];
            int mf = m >> 4, r16 = m & 15;
            int lb = (r16 & 7) * 4;
            int rh = r16 >> 3;
            int ks = kq >> 1, hi = kq & 1;
            int reg = hi * 2 + rh;
            unsigned* dst = &As[(mf * 8 + ks) * 128];
            dst[(lb + 0) * 4 + reg] = f2tf(v.x);
            dst[(lb + 1) * 4 + reg] = f2tf(v.y);
            dst[(lb + 2) * 4 + reg] = f2tf(v.z);
            dst[(lb + 3) * 4 + reg] = f2tf(v.w);
        }
        __syncthreads();
        // ---- compute: 8 k-steps, B fragments straight from global ----
#pragma unroll
        for (int ks = 0; ks < 8; ++ks) {
            uint2 b[4];
#pragma unroll
            for (int j = 0; j < 4; ++j)
                b[j] = *(const uint2*)&Bg[((wn * 4 + j) * 16 + cc * 8 + ks) * 64 + lane * 2];
            uint4 a[4];
#pragma unroll
            for (int i = 0; i < 4; ++i)
                a[i] = *(const uint4*)&As[((wm * 4 + i) * 8 + ks) * 128 + lane * 4];
#pragma unroll
            for (int i = 0; i < 4; ++i)
#pragma unroll
                for (int j = 0; j < 4; ++j) {
                    asm volatile(
                        "mma.sync.aligned.m16n8k8.row.col.f32.tf32.tf32.f32 "
                        "{%0,%1,%2,%3}, {%4,%5,%6,%7}, {%8,%9}, {%0,%1,%2,%3};"
                        : "+f"(c[i][j][0]), "+f"(c[i][j][1]),
                          "+f"(c[i][j][2]), "+f"(c[i][j][3])
                        : "r"(a[i].x), "r"(a[i].y), "r"(a[i].z), "r"(a[i].w),
                          "r"(b[j].x), "r"(b[j].y));
                }
        }
        __syncthreads();
    }
    // ---- epilogue ----
    int n0 = g * 128;
#pragma unroll
    for (int i = 0; i < 4; ++i) {
#pragma unroll
        for (int j = 0; j < 4; ++j) {
            int r = row0 + wm * 64 + i * 16 + (lane >> 2);
            int gcol = n0 + wn * 32 + j * 8 + (lane & 3) * 2;
            float b0 = 0.f, b1 = 0.f;
            if (bias) { b0 = bias[gcol]; b1 = bias[gcol + 1]; }
            if (r < NN) {
                float2 o = make_float2(c[i][j][0] + b0, c[i][j][1] + b1);
                *(float2*)&C[r * ldc + gcol] = o;
            }
            if (r + 8 < NN) {
                float2 o = make_float2(c[i][j][2] + b0, c[i][j][3] + b1);
                *(float2*)&C[(r + 8) * ldc + gcol] = o;
            }
        }
    }
}

// ---------------- GRU gates (torch order r, z, n) ----------------
__global__ void k_gru() {
    int i = blockIdx.x * blockDim.x + threadIdx.x;
    if (i >= NN * HH) return;
    int n = i >> 7, j = i & 127;
    const float* gi = g_gi + n * 384;
    const float* gh = g_gh + n * 384;
    float r = 1.f / (1.f + expf(-(gi[j] + gh[j])));
    float z = 1.f / (1.f + expf(-(gi[128 + j] + gh[128 + j])));
    float nn = tanhf(gi[256 + j] + r * gh[256 + j]);
    float h = g_h[i];
    g_h[i] = (1.f - z) * nn + z * h;
}

// ---------------- classifier + log_softmax ----------------
__global__ void k_cls(const float* __restrict__ lw, const float* __restrict__ lb,
                      float* __restrict__ out) {
    int gt = blockIdx.x * blockDim.x + threadIdx.x;
    int row = gt >> 5;
    int lane = gt & 31;
    if (row >= NN) return;
    const float* hrow = g_h + row * 128;
    float acc[CC];
#pragma unroll
    for (int c = 0; c < CC; ++c) acc[c] = 0.f;
#pragma unroll
    for (int kq = 0; kq < 4; ++kq) {
        int k = lane + kq * 32;
        float hv = hrow[k];
#pragma unroll
        for (int c = 0; c < CC; ++c) acc[c] += hv * lw[c * 128 + k];
    }
#pragma unroll
    for (int c = 0; c < CC; ++c) {
#pragma unroll
        for (int off = 16; off; off >>= 1)
            acc[c] += __shfl_xor_sync(0xffffffffu, acc[c], off);
        acc[c] += lb[c];
    }
    float mx = acc[0];
#pragma unroll
    for (int c = 1; c < CC; ++c) mx = fmaxf(mx, acc[c]);
    float se = 0.f;
#pragma unroll
    for (int c = 0; c < CC; ++c) se += expf(acc[c] - mx);
    float lse = mx + logf(se);
    if (lane < CC) out[row * CC + lane] = acc[lane] - lse;
}

// ---------------- launch ----------------
extern "C" void kernel_launch(void* const* d_in, const int* in_sizes, int n_in,
                              void* d_out, int out_size) {
    const float* x     = (const float*)d_in[0];
    const void*  ei    = d_in[1];
    const float* W     = (const float*)d_in[2];
    const float* w_ih  = (const float*)d_in[3];
    const float* w_hh  = (const float*)d_in[4];
    const float* b_ih  = (const float*)d_in[5];
    const float* b_hh  = (const float*)d_in[6];
    const float* lw    = (const float*)d_in[7];
    const float* lb    = (const float*)d_in[8];
    float* out = (float*)d_out;

    float *p_h, *p_m, *p_agg, *p_gi, *p_gh;
    unsigned *p_Wtp, *p_Wihp, *p_Whhp;
    cudaGetSymbolAddress((void**)&p_h,    g_h);
    cudaGetSymbolAddress((void**)&p_m,    g_m);
    cudaGetSymbolAddress((void**)&p_agg,  g_agg);
    cudaGetSymbolAddress((void**)&p_gi,   g_gi);
    cudaGetSymbolAddress((void**)&p_gh,   g_gh);
    cudaGetSymbolAddress((void**)&p_Wtp,  g_Wtp);
    cudaGetSymbolAddress((void**)&p_Wihp, g_Wihp);
    cudaGetSymbolAddress((void**)&p_Whhp, g_Whhp);

    const int NSCAN = (NN + 255) / 256;   // 196

    k_detect<<<1, 32>>>(ei);
    k_convert<<<(2 * EE + 255) / 256, 256>>>(ei);
    k_pad<<<(NN * HH + 255) / 256, 256>>>(x);
    k_prep<<<256, 256>>>(W, w_ih, w_hh);
    k_zero_deg<<<NSCAN, 256>>>();
    k_hist<<<(EE + 255) / 256, 256>>>();
    k_scan1<<<NSCAN, 256>>>();
    k_scan2<<<1, 256>>>(NSCAN);
    k_scan3<<<NSCAN, 256>>>();
    k_fill<<<(EE + 255) / 256, 256>>>();

    dim3 gm((NN + 127) / 128, 1);
    dim3 gg((NN + 127) / 128, 3);
    for (int l = 0; l < LL; ++l) {
        k_mma<<<gm, 256>>>(p_h, p_Wtp + l * HH * HH, nullptr, p_m, 128);
        k_gather<<<NN, 128>>>();
        k_mma<<<gg, 256>>>(p_agg, p_Wihp, b_ih, p_gi, 384);
        k_mma<<<gg, 256>>>(p_h, p_Whhp, b_hh, p_gh, 384);
        k_gru<<<(NN * HH + 255) / 256, 256>>>();
    }
    k_cls<<<(NN * 32 + 255) / 256, 256>>>(lw, lb, out);
}

// round 7
// speedup vs baseline: 1.6479x; 1.0631x over previous
#include <cuda_runtime.h>
#include <math.h>

#define NN 50000
#define EE 800000
#define HH 128
#define FIN 64
#define CC 16
#define LL 3

// ---------------- scratch (static device globals; no allocation) ----------------
__device__ float g_h[NN * HH];          // hidden state  [N,128]
__device__ float g_m[NN * HH];          // messages      [N,128]
__device__ float g_agg[NN * HH];        // aggregated    [N,128]
__device__ float g_gi[NN * 3 * HH];     // input gates   [N,384] (with b_ih)
__device__ float g_r[NN * HH];          // r gate
__device__ float g_z[NN * HH];          // z gate
__device__ unsigned g_Wtp[LL * HH * HH];   // W^T per layer, tf32 fragment-permuted
__device__ unsigned g_Wihp[3 * HH * HH];   // w_ih tf32 fragment-permuted
__device__ unsigned g_Whhp[3 * HH * HH];   // w_hh tf32 fragment-permuted
__device__ int   g_edge[2 * EE];
__device__ int   g_deg[NN];
__device__ int   g_rowptr[NN + 1];
__device__ int   g_cursor[NN];
__device__ int   g_col[EE];
__device__ int   g_bsum[256];
__device__ int   g_boff[256];
__device__ int   g_is64;

// ---------------- edge dtype probe + normalize ----------------
__global__ void k_detect(const void* ei) {
    if (blockIdx.x == 0 && threadIdx.x == 0) {
        const long long* p64 = (const long long*)ei;
        int ok64 = 1;
        for (int i = 0; i < 64; ++i) {
            long long v = p64[i];
            if (v < 0 || v >= NN) { ok64 = 0; break; }
        }
        g_is64 = ok64;
    }
}

__global__ void k_convert(const void* ei) {
    int e = blockIdx.x * blockDim.x + threadIdx.x;
    if (e < 2 * EE) {
        int v;
        if (g_is64) v = (int)((const long long*)ei)[e];
        else        v = ((const int*)ei)[e];
        g_edge[e] = v;
    }
}

// ---------------- init ----------------
__global__ void k_pad(const float* __restrict__ x) {
    int i = blockIdx.x * blockDim.x + threadIdx.x;
    if (i < NN * HH) {
        int n = i >> 7, k = i & 127;
        g_h[i] = (k < FIN) ? x[n * FIN + k] : 0.f;
    }
}

__device__ __forceinline__ unsigned f2tf(float x) {
    unsigned r;
    asm("cvt.rna.tf32.f32 %0, %1;" : "=r"(r) : "f"(x));
    return r;
}

// Fragment-permuted B layout for mma.m16n8k8 tf32 B operand, full K=128:
//   g = n>>7, nf = (n>>3)&15, nl = n&7; ks = k>>3, hi = (k&7)>>2, c = k&3
//   offset = ((g*16 + nf)*16 + ks)*64 + (nl*4 + c)*2 + hi
__device__ __forceinline__ int bperm_off(int n, int k) {
    int g = n >> 7, nf = (n >> 3) & 15, nl = n & 7;
    int ks = k >> 3, hi = (k & 7) >> 2, c = k & 3;
    return ((g * 16 + nf) * 16 + ks) * 64 + (nl * 4 + c) * 2 + hi;
}

// pre-round + pre-permute all GEMM B operands once
__global__ void k_prep(const float* __restrict__ W,
                       const float* __restrict__ w_ih,
                       const float* __restrict__ w_hh) {
    int i = blockIdx.x * blockDim.x + threadIdx.x;   // 65536 threads
    if (i < LL * HH * HH) {
        int l = i >> 14;
        int rem = i & 16383;
        int n = rem >> 7, k = rem & 127;             // Bt[n][k] = W[l][k][n]
        g_Wtp[(l << 14) + bperm_off(n, k)] = f2tf(W[(l << 14) + k * 128 + n]);
    }
    if (i < 3 * HH * HH) {
        int n = i >> 7, k = i & 127;
        int off = bperm_off(n, k);
        g_Wihp[off] = f2tf(w_ih[i]);
        g_Whhp[off] = f2tf(w_hh[i]);
    }
}

// ---------------- CSR build ----------------
__global__ void k_zero_deg() {
    int i = blockIdx.x * blockDim.x + threadIdx.x;
    if (i < NN) g_deg[i] = 0;
}

__global__ void k_hist() {
    int e = blockIdx.x * blockDim.x + threadIdx.x;
    if (e < EE) atomicAdd(&g_deg[g_edge[EE + e]], 1);
}

__global__ void k_scan1() {
    __shared__ int s[256];
    int t = threadIdx.x;
    int idx = blockIdx.x * 256 + t;
    int v = (idx < NN) ? g_deg[idx] : 0;
    s[t] = v;
    __syncthreads();
#pragma unroll
    for (int off = 1; off < 256; off <<= 1) {
        int add = (t >= off) ? s[t - off] : 0;
        __syncthreads();
        s[t] += add;
        __syncthreads();
    }
    if (idx < NN) g_rowptr[idx] = s[t] - v;
    if (t == 255) g_bsum[blockIdx.x] = s[255];
}

__global__ void k_scan2(int nblocks) {
    __shared__ int s[256];
    int t = threadIdx.x;
    int v = (t < nblocks) ? g_bsum[t] : 0;
    s[t] = v;
    __syncthreads();
#pragma unroll
    for (int off = 1; off < 256; off <<= 1) {
        int add = (t >= off) ? s[t - off] : 0;
        __syncthreads();
        s[t] += add;
        __syncthreads();
    }
    if (t < nblocks) g_boff[t] = s[t] - v;
}

__global__ void k_scan3() {
    int idx = blockIdx.x * 256 + threadIdx.x;
    if (idx < NN) {
        int v = g_rowptr[idx] + g_boff[blockIdx.x];
        g_rowptr[idx] = v;
        g_cursor[idx] = v;
    }
    if (idx == 0) g_rowptr[NN] = EE;
}

__global__ void k_fill() {
    int e = blockIdx.x * blockDim.x + threadIdx.x;
    if (e < EE) {
        int d = g_edge[EE + e];
        int srcn = g_edge[e];
        int pos = atomicAdd(&g_cursor[d], 1);
        g_col[pos] = srcn;
    }
}

// ---------------- aggregation: warp per node, float4 lanes ----------------
__global__ void k_gather() {
    int warp = (blockIdx.x * blockDim.x + threadIdx.x) >> 5;
    int lane = threadIdx.x & 31;
    if (warp >= NN) return;
    int beg = g_rowptr[warp], end = g_rowptr[warp + 1];
    float4 acc = make_float4(0.f, 0.f, 0.f, 0.f);
    int e = beg;
    for (; e + 2 <= end; e += 2) {
        int s0 = g_col[e], s1 = g_col[e + 1];
        float4 v0 = *(const float4*)&g_m[s0 * HH + lane * 4];
        float4 v1 = *(const float4*)&g_m[s1 * HH + lane * 4];
        acc.x += v0.x + v1.x;
        acc.y += v0.y + v1.y;
        acc.z += v0.z + v1.z;
        acc.w += v0.w + v1.w;
    }
    if (e < end) {
        float4 v = *(const float4*)&g_m[g_col[e] * HH + lane * 4];
        acc.x += v.x; acc.y += v.y; acc.z += v.z; acc.w += v.w;
    }
    *(float4*)&g_agg[warp * HH + lane * 4] = acc;
}

// ---------------- shared GEMM machinery (M-tile 64, full K=128, 1 sync) ----------------
// A smem: fragment-permuted [mf(4)][ks(16)][lane(32)][reg(4)] = 8192 u32 = 32KB.
__device__ __forceinline__ void stageA64(unsigned* As, const float* __restrict__ A,
                                         int row0, int t) {
#pragma unroll
    for (int q = 0; q < 8; ++q) {
        int idx = q * 256 + t;
        int m = idx >> 5, kq = idx & 31;
        int row = row0 + m;
        float4 v = make_float4(0.f, 0.f, 0.f, 0.f);
        if (row < NN) v = *(const float4*)&A[row * 128 + kq * 4];
        int mf = m >> 4, r16 = m & 15;
        int lb = (r16 & 7) * 4, rh = r16 >> 3;
        int ks = kq >> 1, hi = kq & 1, reg = hi * 2 + rh;
        unsigned* dst = &As[(mf * 16 + ks) * 128];
        dst[(lb + 0) * 4 + reg] = f2tf(v.x);
        dst[(lb + 1) * 4 + reg] = f2tf(v.y);
        dst[(lb + 2) * 4 + reg] = f2tf(v.z);
        dst[(lb + 3) * 4 + reg] = f2tf(v.w);
    }
}

// one 64x128 group GEMM: c[2][4][4], B fragments straight from global
__device__ __forceinline__ void mmaGroup(const unsigned* As, const unsigned* __restrict__ Bg,
                                         float c[2][4][4], int wm, int wn, int lane) {
#pragma unroll
    for (int i = 0; i < 2; ++i)
#pragma unroll
        for (int j = 0; j < 4; ++j)
#pragma unroll
            for (int r = 0; r < 4; ++r) c[i][j][r] = 0.f;
#pragma unroll
    for (int ks = 0; ks < 16; ++ks) {
        uint2 b[4];
#pragma unroll
        for (int j = 0; j < 4; ++j)
            b[j] = *(const uint2*)&Bg[((wn * 4 + j) * 16 + ks) * 64 + lane * 2];
        uint4 a[2];
#pragma unroll
        for (int i = 0; i < 2; ++i)
            a[i] = *(const uint4*)&As[((wm * 2 + i) * 16 + ks) * 128 + lane * 4];
#pragma unroll
        for (int i = 0; i < 2; ++i)
#pragma unroll
            for (int j = 0; j < 4; ++j) {
                asm volatile(
                    "mma.sync.aligned.m16n8k8.row.col.f32.tf32.tf32.f32 "
                    "{%0,%1,%2,%3}, {%4,%5,%6,%7}, {%8,%9}, {%0,%1,%2,%3};"
                    : "+f"(c[i][j][0]), "+f"(c[i][j][1]),
                      "+f"(c[i][j][2]), "+f"(c[i][j][3])
                    : "r"(a[i].x), "r"(a[i].y), "r"(a[i].z), "r"(a[i].w),
                      "r"(b[j].x), "r"(b[j].y));
            }
    }
}

// ---------------- m = h @ W_l  (grid 782, 1 group) ----------------
__global__ __launch_bounds__(256, 2) void k_mma_m(const unsigned* __restrict__ Bp) {
    __shared__ unsigned As[8192];
    int t = threadIdx.x, lane = t & 31, w = t >> 5;
    int wm = w >> 2, wn = w & 3;
    int row0 = blockIdx.x * 64;
    stageA64(As, g_h, row0, t);
    __syncthreads();
    float c[2][4][4];
    mmaGroup(As, Bp, c, wm, wn, lane);
#pragma unroll
    for (int i = 0; i < 2; ++i)
#pragma unroll
        for (int j = 0; j < 4; ++j) {
            int r = row0 + wm * 32 + i * 16 + (lane >> 2);
            int col = wn * 32 + j * 8 + (lane & 3) * 2;
            if (r < NN)
                *(float2*)&g_m[r * 128 + col] = make_float2(c[i][j][0], c[i][j][1]);
            if (r + 8 < NN)
                *(float2*)&g_m[(r + 8) * 128 + col] = make_float2(c[i][j][2], c[i][j][3]);
        }
}

// ---------------- gi = agg @ w_ih^T + b_ih  (grid 782, 3 groups in-block) ----------------
__global__ __launch_bounds__(256, 2) void k_gi(const unsigned* __restrict__ Bp,
                                               const float* __restrict__ b_ih) {
    __shared__ unsigned As[8192];
    int t = threadIdx.x, lane = t & 31, w = t >> 5;
    int wm = w >> 2, wn = w & 3;
    int row0 = blockIdx.x * 64;
    stageA64(As, g_agg, row0, t);
    __syncthreads();
#pragma unroll
    for (int g = 0; g < 3; ++g) {
        float c[2][4][4];
        mmaGroup(As, Bp + g * 16384, c, wm, wn, lane);
#pragma unroll
        for (int i = 0; i < 2; ++i)
#pragma unroll
            for (int j = 0; j < 4; ++j) {
                int r = row0 + wm * 32 + i * 16 + (lane >> 2);
                int col = wn * 32 + j * 8 + (lane & 3) * 2;
                int gcol = g * 128 + col;
                float b0 = b_ih[gcol], b1 = b_ih[gcol + 1];
                if (r < NN)
                    *(float2*)&g_gi[r * 384 + gcol] =
                        make_float2(c[i][j][0] + b0, c[i][j][1] + b1);
                if (r + 8 < NN)
                    *(float2*)&g_gi[(r + 8) * 384 + gcol] =
                        make_float2(c[i][j][2] + b0, c[i][j][3] + b1);
            }
    }
}

// ---------------- gh GEMM + full GRU update fused (grid 782) ----------------
// group 0 -> r, group 1 -> z, group 2 -> n + h' (in place; block owns its rows)
__global__ __launch_bounds__(256, 2) void k_ghgru(const unsigned* __restrict__ Bp,
                                                  const float* __restrict__ b_hh) {
    __shared__ unsigned As[8192];
    int t = threadIdx.x, lane = t & 31, w = t >> 5;
    int wm = w >> 2, wn = w & 3;
    int row0 = blockIdx.x * 64;
    stageA64(As, g_h, row0, t);
    __syncthreads();
#pragma unroll
    for (int g = 0; g < 3; ++g) {
        float c[2][4][4];
        mmaGroup(As, Bp + g * 16384, c, wm, wn, lane);
#pragma unroll
        for (int i = 0; i < 2; ++i)
#pragma unroll
            for (int j = 0; j < 4; ++j) {
                int r0 = row0 + wm * 32 + i * 16 + (lane >> 2);
                int col = wn * 32 + j * 8 + (lane & 3) * 2;
                float bh0 = b_hh[g * 128 + col], bh1 = b_hh[g * 128 + col + 1];
#pragma unroll
                for (int half = 0; half < 2; ++half) {
                    int row = r0 + half * 8;
                    if (row >= NN) continue;
                    float gh0 = c[i][j][half * 2 + 0] + bh0;
                    float gh1 = c[i][j][half * 2 + 1] + bh1;
                    if (g == 0) {
                        float2 gi = *(const float2*)&g_gi[row * 384 + col];
                        float v0 = 1.f / (1.f + expf(-(gi.x + gh0)));
                        float v1 = 1.f / (1.f + expf(-(gi.y + gh1)));
                        *(float2*)&g_r[row * 128 + col] = make_float2(v0, v1);
                    } else if (g == 1) {
                        float2 gi = *(const float2*)&g_gi[row * 384 + 128 + col];
                        float v0 = 1.f / (1.f + expf(-(gi.x + gh0)));
                        float v1 = 1.f / (1.f + expf(-(gi.y + gh1)));
                        *(float2*)&g_z[row * 128 + col] = make_float2(v0, v1);
                    } else {
                        float2 gi = *(const float2*)&g_gi[row * 384 + 256 + col];
                        float2 rr = *(const float2*)&g_r[row * 128 + col];
                        float2 zz = *(const float2*)&g_z[row * 128 + col];
                        float2 ho = *(const float2*)&g_h[row * 128 + col];
                        float n0 = tanhf(gi.x + rr.x * gh0);
                        float n1 = tanhf(gi.y + rr.y * gh1);
                        float2 o = make_float2((1.f - zz.x) * n0 + zz.x * ho.x,
                                               (1.f - zz.y) * n1 + zz.y * ho.y);
                        *(float2*)&g_h[row * 128 + col] = o;
                    }
                }
            }
    }
}

// ---------------- classifier + log_softmax ----------------
__global__ void k_cls(const float* __restrict__ lw, const float* __restrict__ lb,
                      float* __restrict__ out) {
    int gt = blockIdx.x * blockDim.x + threadIdx.x;
    int row = gt >> 5;
    int lane = gt & 31;
    if (row >= NN) return;
    const float* hrow = g_h + row * 128;
    float acc[CC];
#pragma unroll
    for (int c = 0; c < CC; ++c) acc[c] = 0.f;
#pragma unroll
    for (int kq = 0; kq < 4; ++kq) {
        int k = lane + kq * 32;
        float hv = hrow[k];
#pragma unroll
        for (int c = 0; c < CC; ++c) acc[c] += hv * lw[c * 128 + k];
    }
#pragma unroll
    for (int c = 0; c < CC; ++c) {
#pragma unroll
        for (int off = 16; off; off >>= 1)
            acc[c] += __shfl_xor_sync(0xffffffffu, acc[c], off);
        acc[c] += lb[c];
    }
    float mx = acc[0];
#pragma unroll
    for (int c = 1; c < CC; ++c) mx = fmaxf(mx, acc[c]);
    float se = 0.f;
#pragma unroll
    for (int c = 0; c < CC; ++c) se += expf(acc[c] - mx);
    float lse = mx + logf(se);
    if (lane < CC) out[row * CC + lane] = acc[lane] - lse;
}

// ---------------- launch ----------------
extern "C" void kernel_launch(void* const* d_in, const int* in_sizes, int n_in,
                              void* d_out, int out_size) {
    const float* x     = (const float*)d_in[0];
    const void*  ei    = d_in[1];
    const float* W     = (const float*)d_in[2];
    const float* w_ih  = (const float*)d_in[3];
    const float* w_hh  = (const float*)d_in[4];
    const float* b_ih  = (const float*)d_in[5];
    const float* b_hh  = (const float*)d_in[6];
    const float* lw    = (const float*)d_in[7];
    const float* lb    = (const float*)d_in[8];
    float* out = (float*)d_out;

    unsigned *p_Wtp, *p_Wihp, *p_Whhp;
    cudaGetSymbolAddress((void**)&p_Wtp,  g_Wtp);
    cudaGetSymbolAddress((void**)&p_Wihp, g_Wihp);
    cudaGetSymbolAddress((void**)&p_Whhp, g_Whhp);

    const int NSCAN = (NN + 255) / 256;   // 196
    const int GB = (NN + 63) / 64;        // 782

    k_detect<<<1, 32>>>(ei);
    k_convert<<<(2 * EE + 255) / 256, 256>>>(ei);
    k_pad<<<(NN * HH + 255) / 256, 256>>>(x);
    k_prep<<<256, 256>>>(W, w_ih, w_hh);
    k_zero_deg<<<NSCAN, 256>>>();
    k_hist<<<(EE + 255) / 256, 256>>>();
    k_scan1<<<NSCAN, 256>>>();
    k_scan2<<<1, 256>>>(NSCAN);
    k_scan3<<<NSCAN, 256>>>();
    k_fill<<<(EE + 255) / 256, 256>>>();

    for (int l = 0; l < LL; ++l) {
        k_mma_m<<<GB, 256>>>(p_Wtp + l * HH * HH);
        k_gather<<<(NN * 32 + 255) / 256, 256>>>();
        k_gi<<<GB, 256>>>(p_Wihp, b_ih);
        k_ghgru<<<GB, 256>>>(p_Whhp, b_hh);
    }
    k_cls<<<(NN * 32 + 255) / 256, 256>>>(lw, lb, out);
}